// round 3
// baseline (speedup 1.0000x reference)
#include <cuda_runtime.h>
#include <math.h>

#define Bv  8
#define Tv  32
#define Nv  500
#define Fv  64
#define Hv  128
#define Ev  8000
#define BT  256            // B*T
#define BTN 128000         // B*T*N
#define NNZ (Ev + Nv)

// ---------------- scratch (static device globals: allowed) ----------------
__device__ float  g_xf [BTN * Hv];   // x @ W_gcn            (bt, n, h)
__device__ float  g_res[BTN * Hv];   // x @ W_res + b_res    (bt, n, h)
__device__ float  g_hg [BTN * Hv];   // gelu(gcn agg + b)    (bt, n, h)
__device__ float  g_deg [Nv];
__device__ float  g_dinv[Nv];
__device__ int    g_cnt [Nv];
__device__ int    g_rowptr[Nv + 1];
__device__ int    g_fill[Nv];
__device__ float2 g_ev[NNZ];         // {norm, __int_as_float(src)} CSR by dst
__device__ int    g_is64;            // edge_index dtype flag

__device__ __forceinline__ float gelu_exact(float x) {
    return 0.5f * x * (1.0f + erff(x * 0.7071067811865476f));
}

// Load edge index element i (of 2*E logical elements), either dtype.
__device__ __forceinline__ int load_idx(const void* ei, int i) {
    long long v;
    if (g_is64) v = ((const long long*)ei)[i];
    else        v = ((const int*)ei)[i];
    // clamp: converts any residual dtype mistake into rel_err, not a crash
    if (v < 0) v = 0;
    if (v >= Nv) v = Nv - 1;
    return (int)v;
}

// ---------------- P-1: detect edge_index dtype ----------------
__global__ void p_detect(const void* __restrict__ ei) {
    if (threadIdx.x != 0) return;
    const long long* p = (const long long*)ei;
    int ok64 = 1;
    for (int i = 0; i < 8; ++i) {
        long long v = p[i];
        if (v < 0 || v >= Nv) ok64 = 0;
    }
    g_is64 = ok64;
}

// ---------------- P0: zero counters ----------------
__global__ void p_init() {
    int i = threadIdx.x;
    if (i < Nv) { g_deg[i] = 0.0f; g_cnt[i] = 0; }
}

// ---------------- P1: degree + in-edge counts ----------------
__global__ void p_deg(const void* __restrict__ ei, const float* __restrict__ ew) {
    int e = blockIdx.x * blockDim.x + threadIdx.x;
    if (e >= Ev) return;
    int dst = load_idx(ei, Ev + e);
    atomicAdd(&g_deg[dst], ew[e]);
    atomicAdd(&g_cnt[dst], 1);
}

// ---------------- P2: dinv + prefix scan -> rowptr/fill ----------------
__global__ void p_scan() {
    __shared__ int s[512];
    int tid = threadIdx.x;
    int c = 0;
    if (tid < Nv) {
        float d = g_deg[tid] + 1.0f;           // + self loop weight
        g_dinv[tid] = 1.0f / sqrtf(d);
        c = g_cnt[tid] + 1;                    // + self loop edge
    }
    s[tid] = c;
    __syncthreads();
    for (int off = 1; off < 512; off <<= 1) {
        int v = (tid >= off) ? s[tid - off] : 0;
        __syncthreads();
        s[tid] += v;
        __syncthreads();
    }
    if (tid < Nv) {
        g_rowptr[tid + 1] = s[tid];
        g_fill[tid] = s[tid] - c;
        if (tid == 0) g_rowptr[0] = 0;
    }
}

// ---------------- P3: CSR fill with normalized edge values ----------------
__global__ void p_fill(const void* __restrict__ ei, const float* __restrict__ ew) {
    int e = blockIdx.x * blockDim.x + threadIdx.x;
    if (e >= NNZ) return;
    int src, dst; float w;
    if (e < Ev) { src = load_idx(ei, e); dst = load_idx(ei, Ev + e); w = ew[e]; }
    else        { src = dst = e - Ev; w = 1.0f; }
    float v = g_dinv[src] * w * g_dinv[dst];
    int pos = atomicAdd(&g_fill[dst], 1);
    if (pos >= 0 && pos < NNZ)
        g_ev[pos] = make_float2(v, __int_as_float(src));
}

// ---------------- K2: fused input projections (xf + res) ----------------
__global__ __launch_bounds__(128) void k_inproj(
    const float* __restrict__ x, const float* __restrict__ Wg,
    const float* __restrict__ Wr, const float* __restrict__ br) {
    __shared__ float sx[8][64];
    int h = threadIdx.x;
    float wg[64], wr[64];
#pragma unroll
    for (int i = 0; i < 64; ++i) { wg[i] = Wg[i * Hv + h]; wr[i] = Wr[i * Hv + h]; }
    float brh = br[h];
    int row0 = blockIdx.x * 128;
#pragma unroll 1
    for (int c = 0; c < 16; ++c) {
        int rbase = row0 + c * 8;
        __syncthreads();
        for (int j = h; j < 512; j += 128)
            sx[j >> 6][j & 63] = x[(rbase + (j >> 6)) * Fv + (j & 63)];
        __syncthreads();
#pragma unroll
        for (int r = 0; r < 8; ++r) {
            float ag = 0.0f, ar = 0.0f;
#pragma unroll
            for (int i = 0; i < 64; i += 4) {
                float4 xv = *(const float4*)&sx[r][i];
                ag += xv.x * wg[i + 0]; ar += xv.x * wr[i + 0];
                ag += xv.y * wg[i + 1]; ar += xv.y * wr[i + 1];
                ag += xv.z * wg[i + 2]; ar += xv.z * wr[i + 2];
                ag += xv.w * wg[i + 3]; ar += xv.w * wr[i + 3];
            }
            int row = rbase + r;
            g_xf [row * Hv + h] = ag;
            g_res[row * Hv + h] = ar + brh;
        }
    }
}

// ---------------- K3: GCN aggregate + bias + gelu (shared-staged gather) --
// 16 h-channels per block, static smem 500*16*4 = 32000 B
__global__ __launch_bounds__(128) void k_gcn(const float* __restrict__ bg) {
    __shared__ float sxf[Nv * 16];
    int bt = blockIdx.x;
    int hbase = blockIdx.y * 16;
    int tid = threadIdx.x;
    const float* xsrc = g_xf + bt * (Nv * Hv);
    for (int idx = tid; idx < Nv * 16; idx += 128) {
        int n = idx >> 4, hh = idx & 15;
        sxf[idx] = xsrc[n * Hv + hbase + hh];
    }
    __syncthreads();
    int hh = tid & 15;
    int ns = tid >> 4;               // 0..7
    float bgv = bg[hbase + hh];
    float* dst = g_hg + bt * (Nv * Hv);
    for (int n = ns; n < Nv; n += 8) {
        int rs = g_rowptr[n], re = g_rowptr[n + 1];
        float acc = 0.0f;
        int e = rs;
        for (; e + 1 < re; e += 2) {
            float2 ev0 = g_ev[e];
            float2 ev1 = g_ev[e + 1];
            acc += ev0.x * sxf[__float_as_int(ev0.y) * 16 + hh];
            acc += ev1.x * sxf[__float_as_int(ev1.y) * 16 + hh];
        }
        if (e < re) {
            float2 ev0 = g_ev[e];
            acc += ev0.x * sxf[__float_as_int(ev0.y) * 16 + hh];
        }
        dst[n * Hv + hbase + hh] = gelu_exact(acc + bgv);
    }
}

// ---------------- K4: temporal conv(K=3) + gelu + residual + LayerNorm ----
__global__ __launch_bounds__(128) void k_conv(
    const float* __restrict__ Wt, const float* __restrict__ btmp,
    const float* __restrict__ lnw, const float* __restrict__ lnb,
    float* __restrict__ out) {
    // input staged as [tt=34][i=128][g=2]  (tt = t_in + 1, rows 0 and 33 are pad)
    __shared__ __align__(16) float sh[34 * 256];
    __shared__ float smu[64], srs[64];
    int o = threadIdx.x;
    int p0 = blockIdx.x * 2;
    int b0 = p0 / Nv, n0 = p0 % Nv;
    int b1 = (p0 + 1) / Nv, n1 = (p0 + 1) % Nv;

    // load input tiles (channel o of both pairs, padded in t)
#pragma unroll
    for (int g = 0; g < 2; ++g) {
        int b = g ? b1 : b0, n = g ? n1 : n0;
        sh[0 * 256 + 2 * o + g] = 0.0f;
        sh[33 * 256 + 2 * o + g] = 0.0f;
        for (int t = 0; t < 32; ++t)
            sh[(t + 1) * 256 + 2 * o + g] = g_hg[((b * Tv + t) * Nv + n) * Hv + o];
    }
    __syncthreads();

    float acc0[32], acc1[32];
#pragma unroll
    for (int t = 0; t < 32; ++t) { acc0[t] = 0.0f; acc1[t] = 0.0f; }

    const float* wrow = Wt + o * 384;              // W_temp[o][i][k]
    const float2* shp = (const float2*)sh;         // [tt][i] pairs, stride 128/tt
#pragma unroll 1
    for (int it = 0; it < 16; ++it) {
        float w[24];
#pragma unroll
        for (int j = 0; j < 24; ++j) w[j] = wrow[it * 24 + j];
#pragma unroll
        for (int ii = 0; ii < 8; ++ii) {
            int i = it * 8 + ii;
            float w0 = w[ii * 3 + 0];
            float w1 = w[ii * 3 + 1];
            float w2 = w[ii * 3 + 2];
            const float2* col = shp + i;
            float2 v0 = col[0];
            float2 v1 = col[128];
#pragma unroll
            for (int t = 0; t < 32; ++t) {
                float2 v2 = col[(t + 2) * 128];
                acc0[t] += w0 * v0.x + w1 * v1.x + w2 * v2.x;
                acc1[t] += w0 * v0.y + w1 * v1.y + w2 * v2.y;
                v0 = v1; v1 = v2;
            }
        }
    }
    __syncthreads();   // done reading input; reuse sh as y buffer [64][129]

    float btv = btmp[o];
    float* shy = sh;
#pragma unroll
    for (int t = 0; t < 32; ++t) {
        float h0 = gelu_exact(acc0[t] + btv);
        float h1 = gelu_exact(acc1[t] + btv);
        h0 += g_res[((b0 * Tv + t) * Nv + n0) * Hv + o];
        h1 += g_res[((b1 * Tv + t) * Nv + n1) * Hv + o];
        shy[t * 129 + o] = h0;
        shy[(32 + t) * 129 + o] = h1;
    }
    __syncthreads();

    if (o < 64) {
        int r = o;
        float s1 = 0.0f;
#pragma unroll 8
        for (int j = 0; j < 128; ++j) s1 += shy[r * 129 + j];
        float mu = s1 * (1.0f / 128.0f);
        float s2 = 0.0f;
#pragma unroll 8
        for (int j = 0; j < 128; ++j) {
            float d = shy[r * 129 + j] - mu;
            s2 += d * d;
        }
        smu[r] = mu;
        srs[r] = 1.0f / sqrtf(s2 * (1.0f / 128.0f) + 1e-5f);
    }
    __syncthreads();

    float lw = lnw[o], lb = lnb[o];
#pragma unroll
    for (int g = 0; g < 2; ++g) {
        int b = g ? b1 : b0, n = g ? n1 : n0;
        for (int t = 0; t < 32; ++t) {
            int r = g * 32 + t;
            float v = shy[r * 129 + o];
            out[((b * Tv + t) * Nv + n) * Hv + o] = (v - smu[r]) * srs[r] * lw + lb;
        }
    }
}

// ---------------- launch ----------------
extern "C" void kernel_launch(void* const* d_in, const int* in_sizes, int n_in,
                              void* d_out, int out_size) {
    const float* x   = (const float*)d_in[0];
    const void*  ei  = d_in[1];
    const float* ew  = (const float*)d_in[2];
    const float* Wg  = (const float*)d_in[3];
    const float* bg  = (const float*)d_in[4];
    const float* Wt  = (const float*)d_in[5];
    const float* btm = (const float*)d_in[6];
    const float* lnw = (const float*)d_in[7];
    const float* lnb = (const float*)d_in[8];
    const float* Wr  = (const float*)d_in[9];
    const float* br  = (const float*)d_in[10];
    float* out = (float*)d_out;

    p_detect<<<1, 32>>>(ei);
    p_init<<<1, 512>>>();
    p_deg <<<(Ev + 127) / 128, 128>>>(ei, ew);
    p_scan<<<1, 512>>>();
    p_fill<<<(NNZ + 127) / 128, 128>>>(ei, ew);
    k_inproj<<<1000, 128>>>(x, Wg, Wr, br);
    k_gcn<<<dim3(BT, 8), 128>>>(bg);
    k_conv<<<2000, 128>>>(Wt, btm, lnw, lnb, out);
}

// round 4
// speedup vs baseline: 1.4874x; 1.4874x over previous
#include <cuda_runtime.h>
#include <math.h>

#define Bv  8
#define Tv  32
#define Nv  500
#define Fv  64
#define Hv  128
#define Ev  8000
#define BT  256            // B*T
#define BTN 128000         // B*T*N
#define NNZ (Ev + Nv)

// ---------------- scratch (static device globals: allowed) ----------------
__device__ float  g_xf [BTN * Hv];   // x @ W_gcn            (bt, n, h)
__device__ float  g_res[BTN * Hv];   // x @ W_res + b_res    (bt, n, h)
__device__ float  g_hg [BTN * Hv];   // gelu(gcn agg + b)    (bt, n, h)
__device__ float  g_deg [Nv];
__device__ float  g_dinv[Nv];
__device__ int    g_cnt [Nv];
__device__ int    g_rowptr[Nv + 1];
__device__ int    g_fill[Nv];
__device__ float2 g_ev[NNZ];         // {norm, __int_as_float(src)} CSR by dst
__device__ int    g_is64;            // edge_index dtype flag

// ---------------- helpers ----------------
__device__ __forceinline__ unsigned long long pack2(float lo, float hi) {
    unsigned long long r;
    asm("mov.b64 %0, {%1, %2};" : "=l"(r) : "f"(lo), "f"(hi));
    return r;
}
__device__ __forceinline__ void unpack2(unsigned long long v, float& lo, float& hi) {
    asm("mov.b64 {%0, %1}, %2;" : "=f"(lo), "=f"(hi) : "l"(v));
}
__device__ __forceinline__ void fma2(unsigned long long& d, unsigned long long a,
                                     unsigned long long b) {
    asm("fma.rn.f32x2 %0, %1, %2, %0;" : "+l"(d) : "l"(a), "l"(b));
}
__device__ __forceinline__ float gelu_exact(float x) {
    return 0.5f * x * (1.0f + erff(x * 0.7071067811865476f));
}

// Load edge index element i (of 2*E logical elements), either dtype.
__device__ __forceinline__ int load_idx(const void* ei, int i) {
    long long v;
    if (g_is64) v = ((const long long*)ei)[i];
    else        v = ((const int*)ei)[i];
    if (v < 0) v = 0;
    if (v >= Nv) v = Nv - 1;
    return (int)v;
}

// ---------------- P-1: detect edge_index dtype ----------------
__global__ void p_detect(const void* __restrict__ ei) {
    if (threadIdx.x != 0) return;
    const long long* p = (const long long*)ei;
    int ok64 = 1;
    for (int i = 0; i < 8; ++i) {
        long long v = p[i];
        if (v < 0 || v >= Nv) ok64 = 0;
    }
    g_is64 = ok64;
}

// ---------------- P0: zero counters ----------------
__global__ void p_init() {
    int i = threadIdx.x;
    if (i < Nv) { g_deg[i] = 0.0f; g_cnt[i] = 0; }
}

// ---------------- P1: degree + in-edge counts ----------------
__global__ void p_deg(const void* __restrict__ ei, const float* __restrict__ ew) {
    int e = blockIdx.x * blockDim.x + threadIdx.x;
    if (e >= Ev) return;
    int dst = load_idx(ei, Ev + e);
    atomicAdd(&g_deg[dst], ew[e]);
    atomicAdd(&g_cnt[dst], 1);
}

// ---------------- P2: dinv + prefix scan -> rowptr/fill ----------------
__global__ void p_scan() {
    __shared__ int s[512];
    int tid = threadIdx.x;
    int c = 0;
    if (tid < Nv) {
        float d = g_deg[tid] + 1.0f;           // + self loop weight
        g_dinv[tid] = 1.0f / sqrtf(d);
        c = g_cnt[tid] + 1;                    // + self loop edge
    }
    s[tid] = c;
    __syncthreads();
    for (int off = 1; off < 512; off <<= 1) {
        int v = (tid >= off) ? s[tid - off] : 0;
        __syncthreads();
        s[tid] += v;
        __syncthreads();
    }
    if (tid < Nv) {
        g_rowptr[tid + 1] = s[tid];
        g_fill[tid] = s[tid] - c;
        if (tid == 0) g_rowptr[0] = 0;
    }
}

// ---------------- P3: CSR fill with normalized edge values ----------------
__global__ void p_fill(const void* __restrict__ ei, const float* __restrict__ ew) {
    int e = blockIdx.x * blockDim.x + threadIdx.x;
    if (e >= NNZ) return;
    int src, dst; float w;
    if (e < Ev) { src = load_idx(ei, e); dst = load_idx(ei, Ev + e); w = ew[e]; }
    else        { src = dst = e - Ev; w = 1.0f; }
    float v = g_dinv[src] * w * g_dinv[dst];
    int pos = atomicAdd(&g_fill[dst], 1);
    if (pos >= 0 && pos < NNZ)
        g_ev[pos] = make_float2(v, __int_as_float(src));
}

// ---------------- K2: fused input projections (xf + res), f32x2 packed ----
__global__ __launch_bounds__(128) void k_inproj(
    const float* __restrict__ x, const float* __restrict__ Wg,
    const float* __restrict__ Wr, const float* __restrict__ br) {
    __shared__ float sx[8][64];
    int h = threadIdx.x;
    // packed weights: lo = W_gcn col, hi = W_res col
    unsigned long long wp[64];
#pragma unroll
    for (int i = 0; i < 64; ++i) wp[i] = pack2(Wg[i * Hv + h], Wr[i * Hv + h]);
    float brh = br[h];
    int row0 = blockIdx.x * 128;
#pragma unroll 1
    for (int c = 0; c < 16; ++c) {
        int rbase = row0 + c * 8;
        __syncthreads();
        for (int j = h; j < 512; j += 128)
            sx[j >> 6][j & 63] = x[(rbase + (j >> 6)) * Fv + (j & 63)];
        __syncthreads();
#pragma unroll
        for (int r = 0; r < 8; ++r) {
            unsigned long long acc = 0ULL;
#pragma unroll
            for (int i = 0; i < 64; i += 4) {
                float4 xv = *(const float4*)&sx[r][i];
                fma2(acc, pack2(xv.x, xv.x), wp[i + 0]);
                fma2(acc, pack2(xv.y, xv.y), wp[i + 1]);
                fma2(acc, pack2(xv.z, xv.z), wp[i + 2]);
                fma2(acc, pack2(xv.w, xv.w), wp[i + 3]);
            }
            float ag, ar; unpack2(acc, ag, ar);
            int row = rbase + r;
            g_xf [row * Hv + h] = ag;
            g_res[row * Hv + h] = ar + brh;
        }
    }
}

// ---------------- K3: GCN aggregate + bias + gelu (shared-staged gather) --
// 16 h-channels per block, static smem 500*16*4 = 32000 B
__global__ __launch_bounds__(128) void k_gcn(const float* __restrict__ bg) {
    __shared__ float sxf[Nv * 16];
    int bt = blockIdx.x;
    int hbase = blockIdx.y * 16;
    int tid = threadIdx.x;
    const float* xsrc = g_xf + bt * (Nv * Hv);
    for (int idx = tid; idx < Nv * 16; idx += 128) {
        int n = idx >> 4, hh = idx & 15;
        sxf[idx] = xsrc[n * Hv + hbase + hh];
    }
    __syncthreads();
    int hh = tid & 15;
    int ns = tid >> 4;               // 0..7
    float bgv = bg[hbase + hh];
    float* dst = g_hg + bt * (Nv * Hv);
    for (int n = ns; n < Nv; n += 8) {
        int rs = g_rowptr[n], re = g_rowptr[n + 1];
        float acc = 0.0f;
        int e = rs;
        for (; e + 1 < re; e += 2) {
            float2 ev0 = g_ev[e];
            float2 ev1 = g_ev[e + 1];
            acc += ev0.x * sxf[__float_as_int(ev0.y) * 16 + hh];
            acc += ev1.x * sxf[__float_as_int(ev1.y) * 16 + hh];
        }
        if (e < re) {
            float2 ev0 = g_ev[e];
            acc += ev0.x * sxf[__float_as_int(ev0.y) * 16 + hh];
        }
        dst[n * Hv + hbase + hh] = gelu_exact(acc + bgv);
    }
}

// ---------------- K4: temporal conv(K=3) + gelu + residual + LayerNorm ----
// f32x2: the two (b,n) pairs of the block ride in one packed accumulator.
__global__ __launch_bounds__(128) void k_conv(
    const float* __restrict__ Wt, const float* __restrict__ btmp,
    const float* __restrict__ lnw, const float* __restrict__ lnb,
    float* __restrict__ out) {
    // input staged as [tt=34][i=128][g=2]  (tt = t_in + 1, rows 0 and 33 are pad)
    __shared__ __align__(16) float sh[34 * 256];
    __shared__ float smu[64], srs[64];
    int o = threadIdx.x;
    int p0 = blockIdx.x * 2;
    int b0 = p0 / Nv, n0 = p0 % Nv;
    int b1 = (p0 + 1) / Nv, n1 = (p0 + 1) % Nv;

    // load input tiles (channel o of both pairs, padded in t)
#pragma unroll
    for (int g = 0; g < 2; ++g) {
        int b = g ? b1 : b0, n = g ? n1 : n0;
        sh[0 * 256 + 2 * o + g] = 0.0f;
        sh[33 * 256 + 2 * o + g] = 0.0f;
        for (int t = 0; t < 32; ++t)
            sh[(t + 1) * 256 + 2 * o + g] = g_hg[((b * Tv + t) * Nv + n) * Hv + o];
    }
    __syncthreads();

    unsigned long long acc[32];
#pragma unroll
    for (int t = 0; t < 32; ++t) acc[t] = 0ULL;

    const float* wrow = Wt + o * 384;        // W_temp[o][i][k]
    const unsigned long long* shp = (const unsigned long long*)sh; // [tt][i] pairs
#pragma unroll 1
    for (int it = 0; it < 16; ++it) {
        float w[24];
#pragma unroll
        for (int j = 0; j < 24; j += 4) {
            float4 wv = *(const float4*)&wrow[it * 24 + j];
            w[j + 0] = wv.x; w[j + 1] = wv.y; w[j + 2] = wv.z; w[j + 3] = wv.w;
        }
#pragma unroll
        for (int ii = 0; ii < 8; ++ii) {
            int i = it * 8 + ii;
            unsigned long long w0 = pack2(w[ii * 3 + 0], w[ii * 3 + 0]);
            unsigned long long w1 = pack2(w[ii * 3 + 1], w[ii * 3 + 1]);
            unsigned long long w2 = pack2(w[ii * 3 + 2], w[ii * 3 + 2]);
            const unsigned long long* col = shp + i;   // stride 128 per tt
            unsigned long long v0 = col[0];
            unsigned long long v1 = col[128];
#pragma unroll
            for (int t = 0; t < 32; ++t) {
                unsigned long long v2 = col[(t + 2) * 128];
                fma2(acc[t], w0, v0);
                fma2(acc[t], w1, v1);
                fma2(acc[t], w2, v2);
                v0 = v1; v1 = v2;
            }
        }
    }
    __syncthreads();   // done reading input; reuse sh as y buffer [64][129]

    float btv = btmp[o];
    float* shy = sh;
#pragma unroll
    for (int t = 0; t < 32; ++t) {
        float y0, y1; unpack2(acc[t], y0, y1);
        float h0 = gelu_exact(y0 + btv);
        float h1 = gelu_exact(y1 + btv);
        h0 += g_res[((b0 * Tv + t) * Nv + n0) * Hv + o];
        h1 += g_res[((b1 * Tv + t) * Nv + n1) * Hv + o];
        shy[t * 129 + o] = h0;
        shy[(32 + t) * 129 + o] = h1;
    }
    __syncthreads();

    if (o < 64) {
        int r = o;
        float s1 = 0.0f;
#pragma unroll 8
        for (int j = 0; j < 128; ++j) s1 += shy[r * 129 + j];
        float mu = s1 * (1.0f / 128.0f);
        float s2 = 0.0f;
#pragma unroll 8
        for (int j = 0; j < 128; ++j) {
            float d = shy[r * 129 + j] - mu;
            s2 += d * d;
        }
        smu[r] = mu;
        srs[r] = 1.0f / sqrtf(s2 * (1.0f / 128.0f) + 1e-5f);
    }
    __syncthreads();

    float lw = lnw[o], lb = lnb[o];
#pragma unroll
    for (int g = 0; g < 2; ++g) {
        int b = g ? b1 : b0, n = g ? n1 : n0;
        for (int t = 0; t < 32; ++t) {
            int r = g * 32 + t;
            float v = shy[r * 129 + o];
            out[((b * Tv + t) * Nv + n) * Hv + o] = (v - smu[r]) * srs[r] * lw + lb;
        }
    }
}

// ---------------- launch ----------------
extern "C" void kernel_launch(void* const* d_in, const int* in_sizes, int n_in,
                              void* d_out, int out_size) {
    const float* x   = (const float*)d_in[0];
    const void*  ei  = d_in[1];
    const float* ew  = (const float*)d_in[2];
    const float* Wg  = (const float*)d_in[3];
    const float* bg  = (const float*)d_in[4];
    const float* Wt  = (const float*)d_in[5];
    const float* btm = (const float*)d_in[6];
    const float* lnw = (const float*)d_in[7];
    const float* lnb = (const float*)d_in[8];
    const float* Wr  = (const float*)d_in[9];
    const float* br  = (const float*)d_in[10];
    float* out = (float*)d_out;

    p_detect<<<1, 32>>>(ei);
    p_init<<<1, 512>>>();
    p_deg <<<(Ev + 127) / 128, 128>>>(ei, ew);
    p_scan<<<1, 512>>>();
    p_fill<<<(NNZ + 127) / 128, 128>>>(ei, ew);
    k_inproj<<<1000, 128>>>(x, Wg, Wr, br);
    k_gcn<<<dim3(BT, 8), 128>>>(bg);
    k_conv<<<2000, 128>>>(Wt, btm, lnw, lnb, out);
}